// round 13
// baseline (speedup 1.0000x reference)
#include <cuda_runtime.h>
#include <cstdint>

// Problem constants
#define NN    32
#define CIN   64
#define COUTC 64
#define REDC  2
#define TT    64
#define VV    128
#define KK    (REDC*TT)   // 128

typedef unsigned int uint32;

// Scratch (device globals; no allocation allowed)
__device__ float g_xf[NN*COUTC*TT*VV];      // [n][o][t][v]  67 MB
__device__ float g_a [NN*KK*VV];            // [n][k][v]      2 MB
__device__ float g_b [NN*KK*VV];            // [n][k][w]      2 MB
__device__ float g_xm[(size_t)NN*TT*VV*VV]; // [n][t][v][w] 134 MB
__device__ float g_WrmF[4*16*32*4];         // tf32 A-fragments [mg][kt][lane][4]

// single-MUFU tanh (sm_75+)
__device__ __forceinline__ float fast_tanh(float x) {
    float y;
    asm("tanh.approx.f32 %0, %1;" : "=f"(y) : "f"(x));
    return y;
}

__device__ __forceinline__ uint32 to_tf32(float x) {
    uint32 u;
    asm("cvt.rna.tf32.f32 %0, %1;" : "=r"(u) : "f"(x));
    return u;
}
__device__ __forceinline__ float tf32f(float x) {
    return __uint_as_float(to_tf32(x));
}
__device__ __forceinline__ uint32 to_tf32u(float x) { return to_tf32(x); }

__device__ __forceinline__ void mma_tf32(
    float* c,
    uint32 a0, uint32 a1, uint32 a2, uint32 a3,
    uint32 b0, uint32 b1)
{
    asm volatile(
        "mma.sync.aligned.m16n8k8.row.col.f32.tf32.tf32.f32 "
        "{%0,%1,%2,%3}, {%4,%5,%6,%7}, {%8,%9}, {%0,%1,%2,%3};"
        : "+f"(c[0]), "+f"(c[1]), "+f"(c[2]), "+f"(c[3])
        : "r"(a0), "r"(a1), "r"(a2), "r"(a3), "r"(b0), "r"(b1));
}

__device__ __forceinline__ void cp_async16(void* smem_dst, const void* gmem_src) {
    uint32 d = (uint32)__cvta_generic_to_shared(smem_dst);
    asm volatile("cp.async.cg.shared.global [%0], [%1], 16;" :: "r"(d), "l"(gmem_src));
}
__device__ __forceinline__ void cp_async8(void* smem_dst, const void* gmem_src) {
    uint32 d = (uint32)__cvta_generic_to_shared(smem_dst);
    asm volatile("cp.async.ca.shared.global [%0], [%1], 8;" :: "r"(d), "l"(gmem_src));
}
__device__ __forceinline__ void cp_commit() {
    asm volatile("cp.async.commit_group;");
}
template<int N>
__device__ __forceinline__ void cp_wait() {
    asm volatile("cp.async.wait_group %0;" :: "n"(N));
}

// ---------------------------------------------------------------------------
// kP: build tf32 A-fragments of Wrm for mma.m16n8k8.
// ---------------------------------------------------------------------------
__global__ void kP(const float* __restrict__ Wrm) {
    int idx = blockIdx.x * blockDim.x + threadIdx.x;   // 2048
    if (idx >= 2048) return;
    int lane = idx & 31, kt = (idx >> 5) & 15, mg = idx >> 9;
    int grp = lane >> 2, tig = lane & 3;
    int r0 = mg*16 + grp, r1 = r0 + 8;
    int c0 = kt*8 + tig, c1 = c0 + 4;
    float4 f;
    f.x = tf32f(Wrm[r0*KK + c0]);
    f.y = tf32f(Wrm[r1*KK + c0]);
    f.z = tf32f(Wrm[r0*KK + c1]);
    f.w = tf32f(Wrm[r1*KK + c1]);
    *(float4*)&g_WrmF[idx*4] = f;
}

// ---------------------------------------------------------------------------
// kA (tf32 mma, cp.async staging): xf = Wf @ X + bf; a,b minis on 256 thr.
// smem: Xs [64c][136] + Wfs [64o][68] + wms [4][64]
// ---------------------------------------------------------------------------
#define XAP 136
#define WFP 68
__global__ void __launch_bounds__(256) kA(
    const float* __restrict__ x,
    const float* __restrict__ Wf,  const float* __restrict__ bf,
    const float* __restrict__ Wm1, const float* __restrict__ bm1,
    const float* __restrict__ Wm2, const float* __restrict__ bm2)
{
    extern __shared__ float sa[];
    float* Xs  = sa;                 // [64][136]
    float* Wfs = Xs + CIN*XAP;       // [64][68]
    float* wms = Wfs + COUTC*WFP;    // [4][64]

    const int tid = threadIdx.x;
    const int t = blockIdx.x;
    const int n = blockIdx.y;

    const float* xb = &x[(((size_t)n*CIN)*TT + t)*VV];
    #pragma unroll
    for (int r = 0; r < 8; r++) {
        int e = tid + r*256;
        int c = e >> 5, seg = e & 31;
        cp_async16(&Xs[c*XAP + seg*4], xb + (size_t)c*TT*VV + seg*4);
    }
    #pragma unroll
    for (int r = 0; r < 4; r++) {
        int e = tid + r*256;
        int o = e >> 4, seg = e & 15;
        cp_async16(&Wfs[o*WFP + seg*4], Wf + o*CIN + seg*4);
    }
    if (tid < 32) cp_async16(&wms[tid*4], Wm1 + tid*4);
    else if (tid < 64) cp_async16(&wms[128 + (tid-32)*4], Wm2 + (tid-32)*4);
    cp_commit();
    cp_wait<0>();
    __syncthreads();

    // a/b minis on all 256 threads: 0-127 -> a (Wm1), 128-255 -> b (Wm2)
    {
        const int v = tid & 127;
        const int off = (tid >> 7) * 128;   // 0 -> Wm1 rows, 128 -> Wm2 rows
        float s0 = 0.f, s1 = 0.f;
        #pragma unroll
        for (int c = 0; c < CIN; c++) {
            float xc = Xs[c*XAP + v];
            s0 += wms[off + c]      * xc;
            s1 += wms[off + 64 + c] * xc;
        }
        if (tid < 128) {
            g_a[((size_t)n*KK + t)*VV + v]      = s0 + __ldg(&bm1[0]);
            g_a[((size_t)n*KK + 64 + t)*VV + v] = s1 + __ldg(&bm1[1]);
        } else {
            g_b[((size_t)n*KK + t)*VV + v]      = s0 + __ldg(&bm2[0]);
            g_b[((size_t)n*KK + 64 + t)*VV + v] = s1 + __ldg(&bm2[1]);
        }
    }

    const int warp = tid >> 5, lane = tid & 31;
    const int grp = lane >> 2, tig = lane & 3;
    const int mg = warp & 3;
    const int n0 = (warp >> 2) * 64;

    float acc[8][4];
    #pragma unroll
    for (int j = 0; j < 8; j++)
        #pragma unroll
        for (int q = 0; q < 4; q++) acc[j][q] = 0.0f;

    const int r0 = mg*16 + grp;
    #pragma unroll
    for (int ks = 0; ks < 8; ks++) {
        const int k0 = ks * 8;
        uint32 a0 = to_tf32u(Wfs[r0*WFP + k0 + tig]);
        uint32 a1 = to_tf32u(Wfs[(r0+8)*WFP + k0 + tig]);
        uint32 a2 = to_tf32u(Wfs[r0*WFP + k0 + tig + 4]);
        uint32 a3 = to_tf32u(Wfs[(r0+8)*WFP + k0 + tig + 4]);
        #pragma unroll
        for (int j = 0; j < 8; j++) {
            const int vcol = n0 + j*8 + grp;
            uint32 b0 = to_tf32u(Xs[(k0+tig)*XAP + vcol]);
            uint32 b1 = to_tf32u(Xs[(k0+tig+4)*XAP + vcol]);
            mma_tf32(acc[j], a0, a1, a2, a3, b0, b1);
        }
    }

    const int c_lo = mg*16 + grp, c_hi = c_lo + 8;
    const float bf_lo = __ldg(&bf[c_lo]);
    const float bf_hi = __ldg(&bf[c_hi]);
    #pragma unroll
    for (int j = 0; j < 8; j++) {
        const int v = n0 + j*8 + 2*tig;
        *(float2*)&g_xf[(((size_t)n*COUTC + c_lo)*TT + t)*VV + v] =
            make_float2(acc[j][0] + bf_lo, acc[j][1] + bf_lo);
        *(float2*)&g_xf[(((size_t)n*COUTC + c_hi)*TT + t)*VV + v] =
            make_float2(acc[j][2] + bf_hi, acc[j][3] + bf_hi);
    }
}

// ---------------------------------------------------------------------------
// kB: xm = brm + A + Wrm @ tanh(a-b), tf32 mma.
// Software-pipelined: tanh for ks+1 computed while HMMAs for ks issue.
// smem: bsm [128][136] + ash [128][2] + wfs 32KB = 101 KB
// ---------------------------------------------------------------------------
#define BSMP 136
__global__ void __launch_bounds__(256, 2) kB(
    const float* __restrict__ A, const float* __restrict__ brm)
{
    extern __shared__ float sm[];
    float* bsm = sm;                // [128][136]
    float* ash = bsm + KK*BSMP;     // [128][2]
    float* wfs = ash + KK*2;        // [4][16][32][4]

    const int tid = threadIdx.x;
    const int n  = blockIdx.y;
    const int v0 = blockIdx.x * 2;

    const float* gb = &g_b[(size_t)n*KK*VV];
    #pragma unroll
    for (int r = 0; r < 16; r++) {
        int e = tid + r*256;
        int k = e >> 5, seg = e & 31;
        cp_async16(&bsm[k*BSMP + seg*4], gb + (size_t)k*VV + seg*4);
    }
    if (tid < 128)
        cp_async8(&ash[tid*2], &g_a[((size_t)n*KK + tid)*VV + v0]);
    #pragma unroll
    for (int r = 0; r < 8; r++) {
        int e = tid + r*256;
        cp_async16(&wfs[e*4], &g_WrmF[e*4]);
    }
    cp_commit();
    cp_wait<0>();
    __syncthreads();

    const int warp = tid >> 5, lane = tid & 31;
    const int grp = lane >> 2, tig = lane & 3;
    const int vbit = warp >> 2;
    const int cb = (warp & 3) * 32;

    const int wc0 = cb + grp;

    float acc[4][4][4];
    #pragma unroll
    for (int m = 0; m < 4; m++)
        #pragma unroll
        for (int j = 0; j < 4; j++)
            #pragma unroll
            for (int q = 0; q < 4; q++) acc[m][j][q] = 0.0f;

    // tanh fragment helper: computes u0/u1 for k-step ks
    auto tanh_step = [&](int ks, uint32* u0, uint32* u1) {
        const int k0 = ks * 8;
        const float a_lo = ash[(k0 + tig)*2 + vbit];
        const float a_hi = ash[(k0 + tig + 4)*2 + vbit];
        const float* blo = &bsm[(k0 + tig)*BSMP];
        const float* bhi = &bsm[(k0 + tig + 4)*BSMP];
        #pragma unroll
        for (int j = 0; j < 4; j++) {
            const int wcj = wc0 + j*8;
            u0[j] = to_tf32(fast_tanh(a_lo - blo[wcj]));
            u1[j] = to_tf32(fast_tanh(a_hi - bhi[wcj]));
        }
    };

    uint32 u0c[4], u1c[4];
    tanh_step(0, u0c, u1c);   // prologue

    #pragma unroll 2
    for (int ks = 0; ks < 16; ks++) {
        uint32 af[4][4];
        #pragma unroll
        for (int mg = 0; mg < 4; mg++) {
            float4 f = *(const float4*)&wfs[((mg*16 + ks)*32 + lane)*4];
            af[mg][0] = __float_as_uint(f.x);
            af[mg][1] = __float_as_uint(f.y);
            af[mg][2] = __float_as_uint(f.z);
            af[mg][3] = __float_as_uint(f.w);
        }

        // compute next step's tanh while this step's HMMAs issue
        uint32 u0n[4], u1n[4];
        if (ks < 15) tanh_step(ks + 1, u0n, u1n);

        #pragma unroll
        for (int j = 0; j < 4; j++)
            #pragma unroll
            for (int mg = 0; mg < 4; mg++)
                mma_tf32(acc[mg][j], af[mg][0], af[mg][1], af[mg][2], af[mg][3],
                         u0c[j], u1c[j]);

        #pragma unroll
        for (int j = 0; j < 4; j++) { u0c[j] = u0n[j]; u1c[j] = u1n[j]; }
    }

    const int v = v0 + vbit;
    #pragma unroll
    for (int mg = 0; mg < 4; mg++) {
        const int t_lo = mg*16 + grp, t_hi = t_lo + 8;
        const float bt0 = __ldg(&brm[t_lo]);
        const float bt1 = __ldg(&brm[t_hi]);
        #pragma unroll
        for (int j = 0; j < 4; j++) {
            const int w = cb + j*8 + 2*tig;
            float2 A0 = *(const float2*)&A[((size_t)t_lo*VV + v)*VV + w];
            float2 A1 = *(const float2*)&A[((size_t)t_hi*VV + v)*VV + w];
            float2 r0, r1;
            r0.x = acc[mg][j][0] + bt0 + A0.x;  r0.y = acc[mg][j][1] + bt0 + A0.y;
            r1.x = acc[mg][j][2] + bt1 + A1.x;  r1.y = acc[mg][j][3] + bt1 + A1.y;
            *(float2*)&g_xm[(((size_t)n*TT + t_lo)*VV + v)*VV + w] = r0;
            *(float2*)&g_xm[(((size_t)n*TT + t_hi)*VV + v)*VV + w] = r1;
        }
    }
}

// ---------------------------------------------------------------------------
// kC (tf32 mma + cp.async pipeline): out = xf(64x128v) @ xm(128v x 128w)
// ---------------------------------------------------------------------------
#define FCP 40
#define MCP 136
__global__ void __launch_bounds__(256) kC(float* __restrict__ out) {
    extern __shared__ float sc[];
    float* xfs = sc;                 // [2][64][40]
    float* xms = sc + 2*COUTC*FCP;   // [2][32][136]

    const int tid = threadIdx.x;
    const int t = blockIdx.x;
    const int n = blockIdx.y;

    const float* xf_base = &g_xf[(((size_t)n*COUTC)*TT + t)*VV];
    const float* xm_base = &g_xm[(((size_t)n*TT + t)*VV)*VV];

    auto load_chunk = [&](int ch, int s) {
        const int v0 = ch * 32;
        #pragma unroll
        for (int r = 0; r < 2; r++) {
            int e = tid + r*256;
            int c = e >> 3, seg = e & 7;
            cp_async16(&xfs[(s*COUTC + c)*FCP + seg*4],
                       xf_base + (size_t)c*TT*VV + v0 + seg*4);
        }
        #pragma unroll
        for (int r = 0; r < 4; r++) {
            int e = tid + r*256;
            int vv = e >> 5, seg = e & 31;
            cp_async16(&xms[(s*32 + vv)*MCP + seg*4],
                       xm_base + (size_t)(v0 + vv)*VV + seg*4);
        }
    };

    const int warp = tid >> 5, lane = tid & 31;
    const int grp = lane >> 2, tig = lane & 3;
    const int mg = warp & 3;
    const int n0 = (warp >> 2) * 64;

    float acc[8][4];
    #pragma unroll
    for (int j = 0; j < 8; j++)
        #pragma unroll
        for (int q = 0; q < 4; q++) acc[j][q] = 0.0f;

    load_chunk(0, 0);
    cp_commit();

    const int r0 = mg*16 + grp;
    #pragma unroll 1
    for (int ch = 0; ch < 4; ch++) {
        const int s = ch & 1;
        if (ch < 3) { load_chunk(ch+1, s^1); cp_commit(); }
        if (ch < 3) cp_wait<1>(); else cp_wait<0>();
        __syncthreads();

        const float* xfc = &xfs[s*COUTC*FCP];
        const float* xmc = &xms[s*32*MCP];
        #pragma unroll
        for (int ks = 0; ks < 4; ks++) {
            const int k0 = ks * 8;
            uint32 a0 = to_tf32u(xfc[r0*FCP + k0 + tig]);
            uint32 a1 = to_tf32u(xfc[(r0+8)*FCP + k0 + tig]);
            uint32 a2 = to_tf32u(xfc[r0*FCP + k0 + tig + 4]);
            uint32 a3 = to_tf32u(xfc[(r0+8)*FCP + k0 + tig + 4]);
            #pragma unroll
            for (int j = 0; j < 8; j++) {
                const int wcol = n0 + j*8 + grp;
                uint32 b0 = to_tf32u(xmc[(k0+tig)*MCP + wcol]);
                uint32 b1 = to_tf32u(xmc[(k0+tig+4)*MCP + wcol]);
                mma_tf32(acc[j], a0, a1, a2, a3, b0, b1);
            }
        }
        __syncthreads();
    }

    const int c_lo = mg*16 + grp, c_hi = c_lo + 8;
    #pragma unroll
    for (int j = 0; j < 8; j++) {
        const int w = n0 + j*8 + 2*tig;
        *(float2*)&out[(((size_t)n*COUTC + c_lo)*TT + t)*VV + w] =
            make_float2(acc[j][0], acc[j][1]);
        *(float2*)&out[(((size_t)n*COUTC + c_hi)*TT + t)*VV + w] =
            make_float2(acc[j][2], acc[j][3]);
    }
}

// ---------------------------------------------------------------------------
extern "C" void kernel_launch(void* const* d_in, const int* in_sizes, int n_in,
                              void* d_out, int out_size)
{
    const float* x   = (const float*)d_in[0];
    const float* A   = (const float*)d_in[1];
    const float* Wf  = (const float*)d_in[2];
    const float* bf  = (const float*)d_in[3];
    const float* Wm1 = (const float*)d_in[4];
    const float* bm1 = (const float*)d_in[5];
    const float* Wm2 = (const float*)d_in[6];
    const float* bm2 = (const float*)d_in[7];
    const float* Wrm = (const float*)d_in[8];
    const float* brm = (const float*)d_in[9];
    float* out = (float*)d_out;

    const int ka_smem = (CIN*XAP + COUTC*WFP + 4*64) * (int)sizeof(float);   // 53760
    const int kb_smem = (KK*BSMP + KK*2 + 8192) * (int)sizeof(float);        // 103424
    const int kc_smem = (2*COUTC*FCP + 2*32*MCP) * (int)sizeof(float);       // 55296
    static int attr_set = 0;
    if (!attr_set) {
        cudaFuncSetAttribute(kA, cudaFuncAttributeMaxDynamicSharedMemorySize, ka_smem);
        cudaFuncSetAttribute(kB, cudaFuncAttributeMaxDynamicSharedMemorySize, kb_smem);
        cudaFuncSetAttribute(kC, cudaFuncAttributeMaxDynamicSharedMemorySize, kc_smem);
        attr_set = 1;
    }

    kP<<<8, 256>>>(Wrm);
    kA<<<dim3(TT, NN), 256, ka_smem>>>(x, Wf, bf, Wm1, bm1, Wm2, bm2);
    kB<<<dim3(VV/2, NN), 256, kb_smem>>>(A, brm);
    kC<<<dim3(TT, NN), 256, kc_smem>>>(out);
}